// round 3
// baseline (speedup 1.0000x reference)
#include <cuda_runtime.h>
#include <math.h>

#define Dm 1024
#define Hm 4096
#define Lm 12
#define Vm 50277
#define NB 148
#define NT 1024
#define NWG (NB * 32)            // total warps in grid
#define NTH (NB * NT)            // total threads in grid

// ---------------- global scratch (allocation-free) ----------------
__device__ float g_k[Dm], g_v[Dm], g_r[Dm];
__device__ float g_po[4 * Dm];        // ow partials [chunk][row]
__device__ float g_fk[Hm], g_fr[Dm];
__device__ float g_pf[4 * Dm];        // fv partials [chunk][row]

// ---------------- grid barrier (replay-safe, deterministic) ----------------
__device__ unsigned g_cnt3[3];
__device__ volatile unsigned g_gen;

__device__ __forceinline__ void gsync() {
    __syncthreads();
    if (threadIdx.x == 0) {
        __threadfence();
        unsigned g = g_gen;
        unsigned s = g % 3u;
        if (atomicAdd(&g_cnt3[s], 1u) == (unsigned)(gridDim.x - 1)) {
            g_cnt3[(g + 2u) % 3u] = 0u;   // reset slot for barrier g+2
            __threadfence();
            g_gen = g + 1u;
        } else {
            while (g_gen == g) { }
        }
        __threadfence();
    }
    __syncthreads();
}

// ---------------- L2 prefetch (pipeline next layer's weights) ----------------
__device__ __forceinline__ void pf_l2(const void* p, size_t bytes) {
    const char* c = (const char*)p;
    size_t start = ((size_t)(blockIdx.x * NT + threadIdx.x)) << 7;
    size_t step  = ((size_t)NTH) << 7;
    for (size_t i = start; i < bytes; i += step)
        asm volatile("prefetch.global.L2 [%0];" :: "l"(c + i));
}

// ---------------- reductions ----------------
__device__ __forceinline__ float warp_sum(float v) {
#pragma unroll
    for (int o = 16; o; o >>= 1) v += __shfl_down_sync(0xffffffffu, v, o);
    return v;
}

__device__ __forceinline__ float block_sum(float v, float* sbuf) {
    int lane = threadIdx.x & 31, wid = threadIdx.x >> 5;
    v = warp_sum(v);
    __syncthreads();
    if (lane == 0) sbuf[wid] = v;
    __syncthreads();
    if (wid == 0) {
        float t = sbuf[lane];
        t = warp_sum(t);
        if (lane == 0) sbuf[0] = t;
    }
    __syncthreads();
    return sbuf[0];
}

__device__ __forceinline__ float ln1024(float v, const float* __restrict__ w,
                                        const float* __restrict__ b, float* sbuf) {
    float mu = block_sum(v, sbuf) * (1.0f / Dm);
    float d = v - mu;
    float var = block_sum(d * d, sbuf) * (1.0f / Dm);
    return d * rsqrtf(var + 1e-5f) * w[threadIdx.x] + b[threadIdx.x];
}

// ---------------- dot helpers ----------------
__device__ __forceinline__ float dot8(const float4* __restrict__ w,
                                      const float4* __restrict__ x, int lane) {
    float acc = 0.f;
#pragma unroll
    for (int j = 0; j < 8; j++) {
        float4 a = __ldcs(w + j * 32 + lane);
        float4 c = x[j * 32 + lane];
        acc = fmaf(a.x, c.x, fmaf(a.y, c.y, fmaf(a.z, c.z, fmaf(a.w, c.w, acc))));
    }
    return warp_sum(acc);
}

__device__ __forceinline__ float dot2(const float4* __restrict__ w,
                                      const float4* __restrict__ x, int lane) {
    float acc = 0.f;
#pragma unroll
    for (int j = 0; j < 2; j++) {
        float4 a = __ldcs(w + j * 32 + lane);
        float4 c = x[j * 32 + lane];
        acc = fmaf(a.x, c.x, fmaf(a.y, c.y, fmaf(a.z, c.z, fmaf(a.w, c.w, acc))));
    }
    return warp_sum(acc);
}

// ---------------- the whole network in one persistent kernel ----------------
__global__ __launch_bounds__(NT, 1) void rwkv_all(
    const int* __restrict__ tok, const float* __restrict__ state,
    const float* __restrict__ emb,
    const float* __restrict__ ln0w, const float* __restrict__ ln0b,
    const float* __restrict__ ln1w, const float* __restrict__ ln1b,
    const float* __restrict__ tmk, const float* __restrict__ tmv,
    const float* __restrict__ tmr, const float* __restrict__ tf,
    const float* __restrict__ td,
    const float* __restrict__ kw, const float* __restrict__ vw,
    const float* __restrict__ rw, const float* __restrict__ ow,
    const float* __restrict__ ln2w, const float* __restrict__ ln2b,
    const float* __restrict__ fmk, const float* __restrict__ fmr,
    const float* __restrict__ fkw, const float* __restrict__ fvw,
    const float* __restrict__ frw,
    const float* __restrict__ lnoutw, const float* __restrict__ lnoutb,
    const float* __restrict__ headw,
    float* __restrict__ logits, float* __restrict__ ns)
{
    __shared__ float s_v0[Dm], s_v1[Dm], s_v2[Dm];
    __shared__ float s_fk[Hm];
    __shared__ float s_red[32];

    const int tid = threadIdx.x;
    const int wid = tid >> 5, lane = tid & 31;
    const int gw = blockIdx.x * 32 + wid;
    const bool b0 = (blockIdx.x == 0);

    const size_t DD = (size_t)Dm * Dm * sizeof(float);   // 4MB
    const size_t HD = (size_t)Hm * Dm * sizeof(float);   // 16MB

    // ---- prefetch layer 0 weights (ordered: phase-1 matrices first) ----
    pf_l2(kw, DD); pf_l2(vw, DD); pf_l2(rw, DD);
    pf_l2(ow, DD); pf_l2(fkw, HD); pf_l2(frw, DD); pf_l2(fvw, HD);

    // ---- embed + ln0 (redundant per block; x lives in a register) ----
    float x = ln1024(emb[(size_t)(*tok) * Dm + tid], ln0w, ln0b, s_red);

    for (int l = 0; l < Lm; l++) {
        const float* s = state + (size_t)l * 5 * Dm;
        float* nsl = ns + (size_t)l * 5 * Dm;
        const size_t dd = (size_t)l * Dm * Dm;
        const size_t hd = (size_t)l * Hm * Dm;

        // ---- prefetch next layer's weights (or head chunk) into L2 ----
        if (l + 1 < Lm) {
            const size_t dd2 = (size_t)(l + 1) * Dm * Dm;
            const size_t hd2 = (size_t)(l + 1) * Hm * Dm;
            pf_l2(kw + dd2, DD); pf_l2(vw + dd2, DD); pf_l2(rw + dd2, DD);
            pf_l2(ow + dd2, DD); pf_l2(fkw + hd2, HD);
            pf_l2(frw + dd2, DD); pf_l2(fvw + hd2, HD);
        } else {
            pf_l2(headw, (size_t)52 * 1024 * 1024);   // first 52MB of head
        }

        // ---- phase 1: LN1 + token-mix, then k/v/r matvec ----
        {
            float xx = ln1024(x, ln1w + l * Dm, ln1b + l * Dm, s_red);
            float ss = s[1 * Dm + tid];
            float mk = tmk[l * Dm + tid], mv = tmv[l * Dm + tid], mr = tmr[l * Dm + tid];
            s_v0[tid] = xx * mk + ss * (1.0f - mk);
            s_v1[tid] = xx * mv + ss * (1.0f - mv);
            s_v2[tid] = xx * mr + ss * (1.0f - mr);
            if (b0) nsl[1 * Dm + tid] = xx;
        }
        __syncthreads();
        for (int t = gw; t < 3 * Dm; t += NWG) {
            int mat = t >> 10, row = t & (Dm - 1);
            const float* W = (mat == 0) ? (kw + dd) : (mat == 1) ? (vw + dd) : (rw + dd);
            const float* xv = (mat == 0) ? s_v0 : (mat == 1) ? s_v1 : s_v2;
            float acc = dot8((const float4*)(W + (size_t)row * Dm), (const float4*)xv, lane);
            if (lane == 0) {
                if (mat == 0)      g_k[row] = acc;
                else if (mat == 1) g_v[row] = acc;
                else               g_r[row] = 1.0f / (1.0f + expf(-acc));
            }
        }
        gsync();

        // ---- phase 2: WKV recurrence (redundant) + ow partials (4 K-chunks) ----
        {
            float k = g_k[tid], v = g_v[tid];
            float aa = s[2 * Dm + tid], bb = s[3 * Dm + tid], pp = s[4 * Dm + tid];
            float ww = tf[l * Dm + tid] + k;
            float p = fmaxf(pp, ww);
            float e1 = expf(pp - p), e2 = expf(ww - p);
            float wkv = (e1 * aa + e2 * v) / (e1 * bb + e2);
            float ww2 = pp + td[l * Dm + tid];
            float p2 = fmaxf(ww2, k);
            float f1 = expf(ww2 - p2), f2 = expf(k - p2);
            s_v0[tid] = g_r[tid] * wkv;
            if (b0) {
                nsl[2 * Dm + tid] = f1 * aa + f2 * v;
                nsl[3 * Dm + tid] = f1 * bb + f2;
                nsl[4 * Dm + tid] = p2;
            }
        }
        __syncthreads();
        for (int t = gw; t < 4 * Dm; t += NWG) {       // 1024 rows x 4 K-chunks of 256
            int row = t >> 2, ch = t & 3;
            float acc = dot2((const float4*)(ow + dd + (size_t)row * Dm + ch * 256),
                             (const float4*)(s_v0 + ch * 256), lane);
            if (lane == 0) g_po[ch * Dm + row] = acc;
        }
        gsync();

        // ---- phase 3: residual + LN2 + FFN mix, then fk/fr matvec ----
        x = x + g_po[tid] + g_po[Dm + tid] + g_po[2 * Dm + tid] + g_po[3 * Dm + tid];
        {
            float yy = ln1024(x, ln2w + l * Dm, ln2b + l * Dm, s_red);
            float sf = s[0 * Dm + tid];
            float mk = fmk[l * Dm + tid], mr = fmr[l * Dm + tid];
            s_v0[tid] = yy * mk + sf * (1.0f - mk);
            s_v1[tid] = yy * mr + sf * (1.0f - mr);
            if (b0) nsl[0 * Dm + tid] = yy;
        }
        __syncthreads();
        for (int t = gw; t < Hm + Dm; t += NWG) {
            bool isk = (t < Hm);
            const float* W = isk ? (fkw + hd + (size_t)t * Dm)
                                 : (frw + dd + (size_t)(t - Hm) * Dm);
            float acc = dot8((const float4*)W, (const float4*)(isk ? s_v0 : s_v1), lane);
            if (lane == 0) {
                if (isk) { float u = fmaxf(acc, 0.0f); g_fk[t] = u * u; }
                else     { g_fr[t - Hm] = 1.0f / (1.0f + expf(-acc)); }
            }
        }
        gsync();

        // ---- phase 4: fv partials (K=4096, 4 chunks of 1024) ----
        for (int j = tid; j < Hm; j += NT) s_fk[j] = g_fk[j];
        __syncthreads();
        for (int t = gw; t < 4 * Dm; t += NWG) {
            int row = t >> 2, ch = t & 3;
            float acc = dot8((const float4*)(fvw + hd + (size_t)row * Hm + ch * Dm),
                             (const float4*)(s_fk + ch * Dm), lane);
            if (lane == 0) g_pf[ch * Dm + row] = acc;
        }
        gsync();

        // ---- residual update for next layer ----
        x = x + g_fr[tid] * (g_pf[tid] + g_pf[Dm + tid] + g_pf[2 * Dm + tid] + g_pf[3 * Dm + tid]);
    }

    // ---- final LN + head matvec ----
    {
        float xf = ln1024(x, lnoutw, lnoutb, s_red);
        s_v0[tid] = xf;
    }
    __syncthreads();
    for (int t = gw; t < Vm; t += NWG) {
        float acc = dot8((const float4*)(headw + (size_t)t * Dm), (const float4*)s_v0, lane);
        if (lane == 0) logits[t] = acc;
    }
}

// ---------------- launch ----------------
extern "C" void kernel_launch(void* const* d_in, const int* in_sizes, int n_in,
                              void* d_out, int out_size) {
    const int*   tok    = (const int*)  d_in[0];
    const float* state  = (const float*)d_in[1];
    const float* emb    = (const float*)d_in[2];
    const float* ln0w   = (const float*)d_in[3];
    const float* ln0b   = (const float*)d_in[4];
    const float* ln1w   = (const float*)d_in[5];
    const float* ln1b   = (const float*)d_in[6];
    const float* tmk    = (const float*)d_in[7];
    const float* tmv    = (const float*)d_in[8];
    const float* tmr    = (const float*)d_in[9];
    const float* tf     = (const float*)d_in[10];
    const float* td     = (const float*)d_in[11];
    const float* kw     = (const float*)d_in[12];
    const float* vw     = (const float*)d_in[13];
    const float* rw     = (const float*)d_in[14];
    const float* ow     = (const float*)d_in[15];
    const float* ln2w   = (const float*)d_in[16];
    const float* ln2b   = (const float*)d_in[17];
    const float* fmk    = (const float*)d_in[18];
    const float* fmr    = (const float*)d_in[19];
    const float* fkw    = (const float*)d_in[20];
    const float* fvw    = (const float*)d_in[21];
    const float* frw    = (const float*)d_in[22];
    const float* lnoutw = (const float*)d_in[23];
    const float* lnoutb = (const float*)d_in[24];
    const float* headw  = (const float*)d_in[25];

    float* logits = (float*)d_out;
    float* ns     = (float*)d_out + Vm;

    rwkv_all<<<NB, NT>>>(tok, state, emb, ln0w, ln0b, ln1w, ln1b,
                         tmk, tmv, tmr, tf, td, kw, vw, rw, ow,
                         ln2w, ln2b, fmk, fmr, fkw, fvw, frw,
                         lnoutw, lnoutb, headw, logits, ns);
}

// round 4
// speedup vs baseline: 1.0165x; 1.0165x over previous
#include <cuda_runtime.h>
#include <math.h>

#define Dm 1024
#define Hm 4096
#define Lm 12
#define Vm 50277
#define NB 148
#define NT 1024
#define NWG (NB * 32)            // total warps in grid

// ---------------- global scratch (allocation-free) ----------------
__device__ float g_k[Dm], g_v[Dm], g_r[Dm];
__device__ float g_po[4 * Dm];
__device__ float g_fk[Hm], g_fr[Dm];
__device__ float g_pf[4 * Dm];
__device__ float g_dummy;             // sink for prefetch accumulator

// ---------------- grid barrier (acquire/release, no L1 flush) ----------------
__device__ unsigned g_cnt3[3];
__device__ unsigned g_gen;

__device__ __forceinline__ unsigned ld_acq(const unsigned* p) {
    unsigned v;
    asm volatile("ld.acquire.gpu.global.u32 %0, [%1];" : "=r"(v) : "l"(p) : "memory");
    return v;
}
__device__ __forceinline__ unsigned atom_add_rel(unsigned* p, unsigned a) {
    unsigned v;
    asm volatile("atom.release.gpu.global.add.u32 %0, [%1], %2;" : "=r"(v) : "l"(p), "r"(a) : "memory");
    return v;
}
__device__ __forceinline__ void st_rel(unsigned* p, unsigned v) {
    asm volatile("st.release.gpu.global.u32 [%0], %1;" :: "l"(p), "r"(v) : "memory");
}
__device__ __forceinline__ void st_rlx(unsigned* p, unsigned v) {
    asm volatile("st.relaxed.gpu.global.u32 [%0], %1;" :: "l"(p), "r"(v) : "memory");
}

__device__ __forceinline__ void gsync() {
    __syncthreads();
    if (threadIdx.x == 0) {
        unsigned g = ld_acq(&g_gen);
        unsigned old = atom_add_rel(&g_cnt3[g % 3u], 1u);
        if (old == (unsigned)(NB - 1)) {
            st_rlx(&g_cnt3[(g + 2u) % 3u], 0u);
            st_rel(&g_gen, g + 1u);
        } else {
            while (ld_acq(&g_gen) == g) { }
        }
    }
    __syncthreads();
}

// ---------------- reductions ----------------
__device__ __forceinline__ float warp_sum(float v) {
#pragma unroll
    for (int o = 16; o; o >>= 1) v += __shfl_down_sync(0xffffffffu, v, o);
    return v;
}

__device__ __forceinline__ float block_sum(float v, float* sbuf) {
    int lane = threadIdx.x & 31, wid = threadIdx.x >> 5;
    v = warp_sum(v);
    __syncthreads();
    if (lane == 0) sbuf[wid] = v;
    __syncthreads();
    if (wid == 0) {
        float t = sbuf[lane];
        t = warp_sum(t);
        if (lane == 0) sbuf[0] = t;
    }
    __syncthreads();
    return sbuf[0];
}

__device__ __forceinline__ float ln1024(float v, const float* __restrict__ w,
                                        const float* __restrict__ b, float* sbuf) {
    float mu = block_sum(v, sbuf) * (1.0f / Dm);
    float d = v - mu;
    float var = block_sum(d * d, sbuf) * (1.0f / Dm);
    return d * rsqrtf(var + 1e-5f) * w[threadIdx.x] + b[threadIdx.x];
}

// ---------------- dot helpers (demand reads, evict-first) ----------------
__device__ __forceinline__ float dot8(const float4* __restrict__ w,
                                      const float4* __restrict__ x, int lane) {
    float acc = 0.f;
#pragma unroll
    for (int j = 0; j < 8; j++) {
        float4 a = __ldcs(w + j * 32 + lane);
        float4 c = x[j * 32 + lane];
        acc = fmaf(a.x, c.x, fmaf(a.y, c.y, fmaf(a.z, c.z, fmaf(a.w, c.w, acc))));
    }
    return warp_sum(acc);
}

__device__ __forceinline__ float dot2(const float4* __restrict__ w,
                                      const float4* __restrict__ x, int lane) {
    float acc = 0.f;
#pragma unroll
    for (int j = 0; j < 2; j++) {
        float4 a = __ldcs(w + j * 32 + lane);
        float4 c = x[j * 32 + lane];
        acc = fmaf(a.x, c.x, fmaf(a.y, c.y, fmaf(a.z, c.z, fmaf(a.w, c.w, acc))));
    }
    return warp_sum(acc);
}

// ---------------- prefetch (real L2-filling loads, kept via dummy acc) ----------------
__device__ __forceinline__ float pf8(const float4* __restrict__ w, int lane) {
    float acc = 0.f;
#pragma unroll
    for (int j = 0; j < 8; j++) acc += __ldcg(w + j * 32 + lane).x;
    return acc;
}
__device__ __forceinline__ float pf2(const float4* __restrict__ w, int lane) {
    return __ldcg(w + lane).x + __ldcg(w + 32 + lane).x;
}

// ---------------- the whole network in one persistent kernel ----------------
__global__ __launch_bounds__(NT, 1) void rwkv_all(
    const int* __restrict__ tok, const float* __restrict__ state,
    const float* __restrict__ emb,
    const float* __restrict__ ln0w, const float* __restrict__ ln0b,
    const float* __restrict__ ln1w, const float* __restrict__ ln1b,
    const float* __restrict__ tmk, const float* __restrict__ tmv,
    const float* __restrict__ tmr, const float* __restrict__ tf,
    const float* __restrict__ td,
    const float* __restrict__ kw, const float* __restrict__ vw,
    const float* __restrict__ rw, const float* __restrict__ ow,
    const float* __restrict__ ln2w, const float* __restrict__ ln2b,
    const float* __restrict__ fmk, const float* __restrict__ fmr,
    const float* __restrict__ fkw, const float* __restrict__ fvw,
    const float* __restrict__ frw,
    const float* __restrict__ lnoutw, const float* __restrict__ lnoutb,
    const float* __restrict__ headw,
    float* __restrict__ logits, float* __restrict__ ns)
{
    __shared__ float s_v0[Dm], s_v1[Dm], s_v2[Dm];
    __shared__ float s_fk[Hm];
    __shared__ float s_red[32];

    const int tid = threadIdx.x;
    const int wid = tid >> 5, lane = tid & 31;
    const int gw = blockIdx.x * 32 + wid;
    const bool b0 = (blockIdx.x == 0);
    float pf_acc = 0.f;

    // ---- prefetch layer-0 phase-1 rows (our own future tasks) ----
    for (int t = gw; t < 3 * Dm; t += NWG) {
        int mat = t >> 10, row = t & (Dm - 1);
        const float* W = (mat == 0) ? kw : (mat == 1) ? vw : rw;
        pf_acc += pf8((const float4*)(W + (size_t)row * Dm), lane);
    }

    // ---- embed + ln0 (redundant per block; x lives in a register) ----
    float x = ln1024(emb[(size_t)(*tok) * Dm + tid], ln0w, ln0b, s_red);

    for (int l = 0; l < Lm; l++) {
        const float* s = state + (size_t)l * 5 * Dm;
        float* nsl = ns + (size_t)l * 5 * Dm;
        const size_t dd = (size_t)l * Dm * Dm;
        const size_t hd = (size_t)l * Hm * Dm;

        // ---- phase 1: LN1 + token-mix, then k/v/r matvec ----
        {
            float xx = ln1024(x, ln1w + l * Dm, ln1b + l * Dm, s_red);
            float ss = s[1 * Dm + tid];
            float mk = tmk[l * Dm + tid], mv = tmv[l * Dm + tid], mr = tmr[l * Dm + tid];
            s_v0[tid] = xx * mk + ss * (1.0f - mk);
            s_v1[tid] = xx * mv + ss * (1.0f - mv);
            s_v2[tid] = xx * mr + ss * (1.0f - mr);
            if (b0) nsl[1 * Dm + tid] = xx;
        }
        __syncthreads();
        for (int t = gw; t < 3 * Dm; t += NWG) {
            int mat = t >> 10, row = t & (Dm - 1);
            const float* W = (mat == 0) ? (kw + dd) : (mat == 1) ? (vw + dd) : (rw + dd);
            const float* xv = (mat == 0) ? s_v0 : (mat == 1) ? s_v1 : s_v2;
            float acc = dot8((const float4*)(W + (size_t)row * Dm), (const float4*)xv, lane);
            if (lane == 0) {
                if (mat == 0)      __stcg(&g_k[row], acc);
                else if (mat == 1) __stcg(&g_v[row], acc);
                else               __stcg(&g_r[row], 1.0f / (1.0f + expf(-acc)));
            }
        }
        // prefetch phase 2 (ow rows we will process)
        for (int t = gw; t < 4 * Dm; t += NWG) {
            int row = t >> 2, ch = t & 3;
            pf_acc += pf2((const float4*)(ow + dd + (size_t)row * Dm + ch * 256), lane);
        }
        gsync();

        // ---- phase 2: WKV recurrence (redundant) + ow partials ----
        {
            float k = __ldcg(&g_k[tid]), v = __ldcg(&g_v[tid]);
            float aa = s[2 * Dm + tid], bb = s[3 * Dm + tid], pp = s[4 * Dm + tid];
            float ww = tf[l * Dm + tid] + k;
            float p = fmaxf(pp, ww);
            float e1 = expf(pp - p), e2 = expf(ww - p);
            float wkv = (e1 * aa + e2 * v) / (e1 * bb + e2);
            float ww2 = pp + td[l * Dm + tid];
            float p2 = fmaxf(ww2, k);
            float f1 = expf(ww2 - p2), f2 = expf(k - p2);
            s_v0[tid] = __ldcg(&g_r[tid]) * wkv;
            if (b0) {
                nsl[2 * Dm + tid] = f1 * aa + f2 * v;
                nsl[3 * Dm + tid] = f1 * bb + f2;
                nsl[4 * Dm + tid] = p2;
            }
        }
        __syncthreads();
        for (int t = gw; t < 4 * Dm; t += NWG) {
            int row = t >> 2, ch = t & 3;
            float acc = dot2((const float4*)(ow + dd + (size_t)row * Dm + ch * 256),
                             (const float4*)(s_v0 + ch * 256), lane);
            if (lane == 0) __stcg(&g_po[ch * Dm + row], acc);
        }
        // prefetch phase 3 (fk/fr rows)
        for (int t = gw; t < Hm + Dm; t += NWG) {
            const float* W = (t < Hm) ? (fkw + hd + (size_t)t * Dm)
                                      : (frw + dd + (size_t)(t - Hm) * Dm);
            pf_acc += pf8((const float4*)W, lane);
        }
        gsync();

        // ---- phase 3: residual + LN2 + FFN mix, then fk/fr matvec ----
        x = x + __ldcg(&g_po[tid]) + __ldcg(&g_po[Dm + tid])
              + __ldcg(&g_po[2 * Dm + tid]) + __ldcg(&g_po[3 * Dm + tid]);
        {
            float yy = ln1024(x, ln2w + l * Dm, ln2b + l * Dm, s_red);
            float sf = s[0 * Dm + tid];
            float mk = fmk[l * Dm + tid], mr = fmr[l * Dm + tid];
            s_v0[tid] = yy * mk + sf * (1.0f - mk);
            s_v1[tid] = yy * mr + sf * (1.0f - mr);
            if (b0) nsl[0 * Dm + tid] = yy;
        }
        __syncthreads();
        for (int t = gw; t < Hm + Dm; t += NWG) {
            bool isk = (t < Hm);
            const float* W = isk ? (fkw + hd + (size_t)t * Dm)
                                 : (frw + dd + (size_t)(t - Hm) * Dm);
            float acc = dot8((const float4*)W, (const float4*)(isk ? s_v0 : s_v1), lane);
            if (lane == 0) {
                if (isk) { float u = fmaxf(acc, 0.0f); __stcg(&g_fk[t], u * u); }
                else     { __stcg(&g_fr[t - Hm], 1.0f / (1.0f + expf(-acc))); }
            }
        }
        // prefetch phase 4 (fv chunks)
        for (int t = gw; t < 4 * Dm; t += NWG) {
            int row = t >> 2, ch = t & 3;
            pf_acc += pf8((const float4*)(fvw + hd + (size_t)row * Hm + ch * Dm), lane);
        }
        gsync();

        // ---- phase 4: fv partials (K=4096, 4 chunks of 1024) ----
        for (int j = tid; j < Hm; j += NT) s_fk[j] = __ldcg(&g_fk[j]);
        __syncthreads();
        for (int t = gw; t < 4 * Dm; t += NWG) {
            int row = t >> 2, ch = t & 3;
            float acc = dot8((const float4*)(fvw + hd + (size_t)row * Hm + ch * Dm),
                             (const float4*)(s_fk + ch * Dm), lane);
            if (lane == 0) __stcg(&g_pf[ch * Dm + row], acc);
        }
        // prefetch next layer's phase 1, or first head rows
        if (l + 1 < Lm) {
            const size_t dd2 = (size_t)(l + 1) * Dm * Dm;
            for (int t = gw; t < 3 * Dm; t += NWG) {
                int mat = t >> 10, row = t & (Dm - 1);
                const float* W = (mat == 0) ? (kw + dd2) : (mat == 1) ? (vw + dd2) : (rw + dd2);
                pf_acc += pf8((const float4*)(W + (size_t)row * Dm), lane);
            }
        } else {
            pf_acc += pf8((const float4*)(headw + (size_t)gw * Dm), lane);
            if (gw + NWG < Vm)
                pf_acc += pf8((const float4*)(headw + (size_t)(gw + NWG) * Dm), lane);
        }
        gsync();

        // ---- residual update for next layer ----
        x = x + __ldcg(&g_fr[tid]) * (__ldcg(&g_pf[tid]) + __ldcg(&g_pf[Dm + tid])
              + __ldcg(&g_pf[2 * Dm + tid]) + __ldcg(&g_pf[3 * Dm + tid]));
    }

    // ---- final LN + head matvec ----
    {
        float xf = ln1024(x, lnoutw, lnoutb, s_red);
        s_v0[tid] = xf;
    }
    __syncthreads();
    for (int t = gw; t < Vm; t += NWG) {
        float acc = dot8((const float4*)(headw + (size_t)t * Dm), (const float4*)s_v0, lane);
        if (lane == 0) logits[t] = acc;
    }

    g_dummy = pf_acc;   // keep prefetch loads alive (never read)
}

// ---------------- launch ----------------
extern "C" void kernel_launch(void* const* d_in, const int* in_sizes, int n_in,
                              void* d_out, int out_size) {
    const int*   tok    = (const int*)  d_in[0];
    const float* state  = (const float*)d_in[1];
    const float* emb    = (const float*)d_in[2];
    const float* ln0w   = (const float*)d_in[3];
    const float* ln0b   = (const float*)d_in[4];
    const float* ln1w   = (const float*)d_in[5];
    const float* ln1b   = (const float*)d_in[6];
    const float* tmk    = (const float*)d_in[7];
    const float* tmv    = (const float*)d_in[8];
    const float* tmr    = (const float*)d_in[9];
    const float* tf     = (const float*)d_in[10];
    const float* td     = (const float*)d_in[11];
    const float* kw     = (const float*)d_in[12];
    const float* vw     = (const float*)d_in[13];
    const float* rw     = (const float*)d_in[14];
    const float* ow     = (const float*)d_in[15];
    const float* ln2w   = (const float*)d_in[16];
    const float* ln2b   = (const float*)d_in[17];
    const float* fmk    = (const float*)d_in[18];
    const float* fmr    = (const float*)d_in[19];
    const float* fkw    = (const float*)d_in[20];
    const float* fvw    = (const float*)d_in[21];
    const float* frw    = (const float*)d_in[22];
    const float* lnoutw = (const float*)d_in[23];
    const float* lnoutb = (const float*)d_in[24];
    const float* headw  = (const float*)d_in[25];

    float* logits = (float*)d_out;
    float* ns     = (float*)d_out + Vm;

    rwkv_all<<<NB, NT>>>(tok, state, emb, ln0w, ln0b, ln1w, ln1b,
                         tmk, tmv, tmr, tf, td, kw, vw, rw, ow,
                         ln2w, ln2b, fmk, fmr, fkw, fvw, frw,
                         lnoutw, lnoutb, headw, logits, ns);
}

// round 5
// speedup vs baseline: 1.1159x; 1.0978x over previous
#include <cuda_runtime.h>
#include <math.h>

#define Dm 1024
#define Hm 4096
#define Lm 12
#define Vm 50277
#define NB 148
#define NT 1024
#define NWG (NB * 32)            // total warps in grid
#define NTH (NB * NT)            // total threads in grid

// ---------------- global scratch (allocation-free) ----------------
__device__ float g_k[Dm], g_v[Dm], g_r[Dm];
__device__ float g_po[4 * Dm];
__device__ float g_fk[Hm], g_fr[Dm];
__device__ float g_pf[4 * Dm];

// ---------------- grid barrier (acquire/release, no L1 flush) ----------------
__device__ unsigned g_cnt3[3];
__device__ unsigned g_gen;

__device__ __forceinline__ unsigned ld_acq(const unsigned* p) {
    unsigned v;
    asm volatile("ld.acquire.gpu.global.u32 %0, [%1];" : "=r"(v) : "l"(p) : "memory");
    return v;
}
__device__ __forceinline__ unsigned atom_add_rel(unsigned* p, unsigned a) {
    unsigned v;
    asm volatile("atom.release.gpu.global.add.u32 %0, [%1], %2;" : "=r"(v) : "l"(p), "r"(a) : "memory");
    return v;
}
__device__ __forceinline__ void st_rel(unsigned* p, unsigned v) {
    asm volatile("st.release.gpu.global.u32 [%0], %1;" :: "l"(p), "r"(v) : "memory");
}
__device__ __forceinline__ void st_rlx(unsigned* p, unsigned v) {
    asm volatile("st.relaxed.gpu.global.u32 [%0], %1;" :: "l"(p), "r"(v) : "memory");
}

__device__ __forceinline__ void gsync() {
    __syncthreads();
    if (threadIdx.x == 0) {
        unsigned g = ld_acq(&g_gen);
        unsigned old = atom_add_rel(&g_cnt3[g % 3u], 1u);
        if (old == (unsigned)(NB - 1)) {
            st_rlx(&g_cnt3[(g + 2u) % 3u], 0u);
            st_rel(&g_gen, g + 1u);
        } else {
            while (ld_acq(&g_gen) == g) { }
        }
    }
    __syncthreads();
}

// ---------------- fire-and-forget L2 prefetch (no reg, no scoreboard) ----------------
__device__ __forceinline__ void pf_l2(const void* p, size_t bytes) {
    const char* c = (const char*)p;
    size_t start = ((size_t)(blockIdx.x * NT + threadIdx.x)) << 7;
    size_t step  = ((size_t)NTH) << 7;
    for (size_t i = start; i < bytes; i += step)
        asm volatile("prefetch.global.L2 [%0];" :: "l"(c + i));
}

// ---------------- reductions ----------------
__device__ __forceinline__ float warp_sum(float v) {
#pragma unroll
    for (int o = 16; o; o >>= 1) v += __shfl_down_sync(0xffffffffu, v, o);
    return v;
}

__device__ __forceinline__ float block_sum(float v, float* sbuf) {
    int lane = threadIdx.x & 31, wid = threadIdx.x >> 5;
    v = warp_sum(v);
    __syncthreads();
    if (lane == 0) sbuf[wid] = v;
    __syncthreads();
    if (wid == 0) {
        float t = sbuf[lane];
        t = warp_sum(t);
        if (lane == 0) sbuf[0] = t;
    }
    __syncthreads();
    return sbuf[0];
}

__device__ __forceinline__ float ln1024(float v, const float* __restrict__ w,
                                        const float* __restrict__ b, float* sbuf) {
    float mu = block_sum(v, sbuf) * (1.0f / Dm);
    float d = v - mu;
    float var = block_sum(d * d, sbuf) * (1.0f / Dm);
    return d * rsqrtf(var + 1e-5f) * w[threadIdx.x] + b[threadIdx.x];
}

// ---------------- dot helpers ----------------
__device__ __forceinline__ float dot8(const float4* __restrict__ w,
                                      const float4* __restrict__ x, int lane) {
    float acc = 0.f;
#pragma unroll
    for (int j = 0; j < 8; j++) {
        float4 a = __ldcs(w + j * 32 + lane);
        float4 c = x[j * 32 + lane];
        acc = fmaf(a.x, c.x, fmaf(a.y, c.y, fmaf(a.z, c.z, fmaf(a.w, c.w, acc))));
    }
    return warp_sum(acc);
}

__device__ __forceinline__ float dot2(const float4* __restrict__ w,
                                      const float4* __restrict__ x, int lane) {
    float acc = 0.f;
#pragma unroll
    for (int j = 0; j < 2; j++) {
        float4 a = __ldcs(w + j * 32 + lane);
        float4 c = x[j * 32 + lane];
        acc = fmaf(a.x, c.x, fmaf(a.y, c.y, fmaf(a.z, c.z, fmaf(a.w, c.w, acc))));
    }
    return warp_sum(acc);
}

// ---------------- the whole network in one persistent kernel ----------------
__global__ __launch_bounds__(NT, 1) void rwkv_all(
    const int* __restrict__ tok, const float* __restrict__ state,
    const float* __restrict__ emb,
    const float* __restrict__ ln0w, const float* __restrict__ ln0b,
    const float* __restrict__ ln1w, const float* __restrict__ ln1b,
    const float* __restrict__ tmk, const float* __restrict__ tmv,
    const float* __restrict__ tmr, const float* __restrict__ tf,
    const float* __restrict__ td,
    const float* __restrict__ kw, const float* __restrict__ vw,
    const float* __restrict__ rw, const float* __restrict__ ow,
    const float* __restrict__ ln2w, const float* __restrict__ ln2b,
    const float* __restrict__ fmk, const float* __restrict__ fmr,
    const float* __restrict__ fkw, const float* __restrict__ fvw,
    const float* __restrict__ frw,
    const float* __restrict__ lnoutw, const float* __restrict__ lnoutb,
    const float* __restrict__ headw,
    float* __restrict__ logits, float* __restrict__ ns)
{
    __shared__ float s_v0[Dm], s_v1[Dm], s_v2[Dm];
    __shared__ float s_fk[Hm];
    __shared__ float s_red[32];

    const int tid = threadIdx.x;
    const int wid = tid >> 5, lane = tid & 31;
    const int gw = blockIdx.x * 32 + wid;
    const bool b0 = (blockIdx.x == 0);

    const size_t DD = (size_t)Dm * Dm * sizeof(float);   // 4MB
    const size_t HD = (size_t)Hm * Dm * sizeof(float);   // 16MB

    // ---- warm L2 with layer-0 phase-1 weights (non-blocking hints) ----
    pf_l2(kw, DD); pf_l2(vw, DD); pf_l2(rw, DD);

    // ---- embed + ln0 (redundant per block; x lives in a register) ----
    float x = ln1024(emb[(size_t)(*tok) * Dm + tid], ln0w, ln0b, s_red);

    for (int l = 0; l < Lm; l++) {
        const float* s = state + (size_t)l * 5 * Dm;
        float* nsl = ns + (size_t)l * 5 * Dm;
        const size_t dd = (size_t)l * Dm * Dm;
        const size_t hd = (size_t)l * Hm * Dm;

        // ---- phase 1: LN1 + token-mix, then k/v/r matvec ----
        {
            float xx = ln1024(x, ln1w + l * Dm, ln1b + l * Dm, s_red);
            float ss = s[1 * Dm + tid];
            float mk = tmk[l * Dm + tid], mv = tmv[l * Dm + tid], mr = tmr[l * Dm + tid];
            s_v0[tid] = xx * mk + ss * (1.0f - mk);
            s_v1[tid] = xx * mv + ss * (1.0f - mv);
            s_v2[tid] = xx * mr + ss * (1.0f - mr);
            if (b0) nsl[1 * Dm + tid] = xx;
        }
        __syncthreads();
        for (int t = gw; t < 3 * Dm; t += NWG) {
            int mat = t >> 10, row = t & (Dm - 1);
            const float* W = (mat == 0) ? (kw + dd) : (mat == 1) ? (vw + dd) : (rw + dd);
            const float* xv = (mat == 0) ? s_v0 : (mat == 1) ? s_v1 : s_v2;
            float acc = dot8((const float4*)(W + (size_t)row * Dm), (const float4*)xv, lane);
            if (lane == 0) {
                if (mat == 0)      __stcg(&g_k[row], acc);
                else if (mat == 1) __stcg(&g_v[row], acc);
                else               __stcg(&g_r[row], 1.0f / (1.0f + expf(-acc)));
            }
        }
        pf_l2(ow + dd, DD);                       // next phase's slab, non-blocking
        gsync();

        // ---- phase 2: WKV recurrence (redundant) + ow partials ----
        {
            float k = __ldcg(&g_k[tid]), v = __ldcg(&g_v[tid]);
            float aa = s[2 * Dm + tid], bb = s[3 * Dm + tid], pp = s[4 * Dm + tid];
            float ww = tf[l * Dm + tid] + k;
            float p = fmaxf(pp, ww);
            float e1 = expf(pp - p), e2 = expf(ww - p);
            float wkv = (e1 * aa + e2 * v) / (e1 * bb + e2);
            float ww2 = pp + td[l * Dm + tid];
            float p2 = fmaxf(ww2, k);
            float f1 = expf(ww2 - p2), f2 = expf(k - p2);
            s_v0[tid] = __ldcg(&g_r[tid]) * wkv;
            if (b0) {
                nsl[2 * Dm + tid] = f1 * aa + f2 * v;
                nsl[3 * Dm + tid] = f1 * bb + f2;
                nsl[4 * Dm + tid] = p2;
            }
        }
        __syncthreads();
        for (int t = gw; t < 4 * Dm; t += NWG) {
            int row = t >> 2, ch = t & 3;
            float acc = dot2((const float4*)(ow + dd + (size_t)row * Dm + ch * 256),
                             (const float4*)(s_v0 + ch * 256), lane);
            if (lane == 0) __stcg(&g_po[ch * Dm + row], acc);
        }
        pf_l2(fkw + hd, HD); pf_l2(frw + dd, DD); // next phase's slab
        gsync();

        // ---- phase 3: residual + LN2 + FFN mix, then fk/fr matvec ----
        x = x + __ldcg(&g_po[tid]) + __ldcg(&g_po[Dm + tid])
              + __ldcg(&g_po[2 * Dm + tid]) + __ldcg(&g_po[3 * Dm + tid]);
        {
            float yy = ln1024(x, ln2w + l * Dm, ln2b + l * Dm, s_red);
            float sf = s[0 * Dm + tid];
            float mk = fmk[l * Dm + tid], mr = fmr[l * Dm + tid];
            s_v0[tid] = yy * mk + sf * (1.0f - mk);
            s_v1[tid] = yy * mr + sf * (1.0f - mr);
            if (b0) nsl[0 * Dm + tid] = yy;
        }
        __syncthreads();
        for (int t = gw; t < Hm + Dm; t += NWG) {
            bool isk = (t < Hm);
            const float* W = isk ? (fkw + hd + (size_t)t * Dm)
                                 : (frw + dd + (size_t)(t - Hm) * Dm);
            float acc = dot8((const float4*)W, (const float4*)(isk ? s_v0 : s_v1), lane);
            if (lane == 0) {
                if (isk) { float u = fmaxf(acc, 0.0f); __stcg(&g_fk[t], u * u); }
                else     { __stcg(&g_fr[t - Hm], 1.0f / (1.0f + expf(-acc))); }
            }
        }
        pf_l2(fvw + hd, HD);                      // next phase's slab
        gsync();

        // ---- phase 4: fv partials (K=4096, 4 chunks of 1024) ----
        for (int j = tid; j < Hm; j += NT) s_fk[j] = __ldcg(&g_fk[j]);
        __syncthreads();
        for (int t = gw; t < 4 * Dm; t += NWG) {
            int row = t >> 2, ch = t & 3;
            float acc = dot8((const float4*)(fvw + hd + (size_t)row * Hm + ch * Dm),
                             (const float4*)(s_fk + ch * Dm), lane);
            if (lane == 0) __stcg(&g_pf[ch * Dm + row], acc);
        }
        if (l + 1 < Lm) {                         // next layer's phase-1 slab
            const size_t dd2 = (size_t)(l + 1) * Dm * Dm;
            pf_l2(kw + dd2, DD); pf_l2(vw + dd2, DD); pf_l2(rw + dd2, DD);
        }
        if (l >= Lm - 4) {                        // drip-prefetch head (last 4 layers, 15MB each)
            const size_t CH = (size_t)15 * 1024 * 1024;
            pf_l2((const char*)headw + (size_t)(l - (Lm - 4)) * CH, CH);
        }
        gsync();

        // ---- residual update for next layer ----
        x = x + __ldcg(&g_fr[tid]) * (__ldcg(&g_pf[tid]) + __ldcg(&g_pf[Dm + tid])
              + __ldcg(&g_pf[2 * Dm + tid]) + __ldcg(&g_pf[3 * Dm + tid]));
    }

    // ---- final LN + head matvec (2 rows/warp in flight) ----
    {
        float xf = ln1024(x, lnoutw, lnoutb, s_red);
        s_v0[tid] = xf;
    }
    __syncthreads();
    for (int t = gw; t < Vm; t += 2 * NWG) {
        int t2 = t + NWG;
        const float4* w0 = (const float4*)(headw + (size_t)t * Dm);
        const float4* x4 = (const float4*)s_v0;
        float a0 = 0.f, a1 = 0.f;
        if (t2 < Vm) {
            const float4* w1 = (const float4*)(headw + (size_t)t2 * Dm);
#pragma unroll
            for (int j = 0; j < 8; j++) {
                float4 p = __ldcs(w0 + j * 32 + lane);
                float4 q = __ldcs(w1 + j * 32 + lane);
                float4 c = x4[j * 32 + lane];
                a0 = fmaf(p.x, c.x, fmaf(p.y, c.y, fmaf(p.z, c.z, fmaf(p.w, c.w, a0))));
                a1 = fmaf(q.x, c.x, fmaf(q.y, c.y, fmaf(q.z, c.z, fmaf(q.w, c.w, a1))));
            }
            a0 = warp_sum(a0); a1 = warp_sum(a1);
            if (lane == 0) { logits[t] = a0; logits[t2] = a1; }
        } else {
#pragma unroll
            for (int j = 0; j < 8; j++) {
                float4 p = __ldcs(w0 + j * 32 + lane);
                float4 c = x4[j * 32 + lane];
                a0 = fmaf(p.x, c.x, fmaf(p.y, c.y, fmaf(p.z, c.z, fmaf(p.w, c.w, a0))));
            }
            a0 = warp_sum(a0);
            if (lane == 0) logits[t] = a0;
        }
    }
}

// ---------------- launch ----------------
extern "C" void kernel_launch(void* const* d_in, const int* in_sizes, int n_in,
                              void* d_out, int out_size) {
    const int*   tok    = (const int*)  d_in[0];
    const float* state  = (const float*)d_in[1];
    const float* emb    = (const float*)d_in[2];
    const float* ln0w   = (const float*)d_in[3];
    const float* ln0b   = (const float*)d_in[4];
    const float* ln1w   = (const float*)d_in[5];
    const float* ln1b   = (const float*)d_in[6];
    const float* tmk    = (const float*)d_in[7];
    const float* tmv    = (const float*)d_in[8];
    const float* tmr    = (const float*)d_in[9];
    const float* tf     = (const float*)d_in[10];
    const float* td     = (const float*)d_in[11];
    const float* kw     = (const float*)d_in[12];
    const float* vw     = (const float*)d_in[13];
    const float* rw     = (const float*)d_in[14];
    const float* ow     = (const float*)d_in[15];
    const float* ln2w   = (const float*)d_in[16];
    const float* ln2b   = (const float*)d_in[17];
    const float* fmk    = (const float*)d_in[18];
    const float* fmr    = (const float*)d_in[19];
    const float* fkw    = (const float*)d_in[20];
    const float* fvw    = (const float*)d_in[21];
    const float* frw    = (const float*)d_in[22];
    const float* lnoutw = (const float*)d_in[23];
    const float* lnoutb = (const float*)d_in[24];
    const float* headw  = (const float*)d_in[25];

    float* logits = (float*)d_out;
    float* ns     = (float*)d_out + Vm;

    rwkv_all<<<NB, NT>>>(tok, state, emb, ln0w, ln0b, ln1w, ln1b,
                         tmk, tmv, tmr, tf, td, kw, vw, rw, ow,
                         ln2w, ln2b, fmk, fmr, fkw, fvw, frw,
                         lnoutw, lnoutb, headw, logits, ns);
}